// round 11
// baseline (speedup 1.0000x reference)
#include <cuda_runtime.h>
#include <cuda_bf16.h>

// Shapes fixed by problem: T=1024, B=8, D=64, N=64
#define T_DIM 1024
#define B_DIM 8
#define CH    32                   // chunks over T
#define TC    (T_DIM / CH)         // 32 timesteps per chunk
#define EPSV  1e-8f

// Scratch (device globals, allocation-free)
__device__ float  gLogAgg[CH * B_DIM * 64];  // log of per-chunk alpha product
__device__ float  gWraw[T_DIM * B_DIM * 64]; // k * chunk-local cumprod (2 MB)
__device__ float4 gCraw[CH * B_DIM * 1024];  // unscaled chunk outer sums (4 MB)

// ---------------------------------------------------------------------------
// K1: per (c,b): chunk-local multiply-scan -> w_raw, chunk outer sums -> gCraw,
//     chunk log product -> gLogAgg. No cross-chunk dependencies.
// grid (CH,B), 512 threads.
// ---------------------------------------------------------------------------
__global__ void __launch_bounds__(512)
k_chunk(const float* __restrict__ vv,
        const float* __restrict__ kk,
        const float* __restrict__ alpha) {
    const int c = blockIdx.x, b = blockIdx.y;
    const int tid = threadIdx.x;

    __shared__ float  s_v[TC][64];
    __shared__ float4 s_w4[TC][16];
    __shared__ float  s_tot[8][64];
    float* s_w = (float*)s_w4;

    // v tile load (coalesced)
    for (int i = tid; i < TC * 64; i += 512) {
        int t = i >> 6, j = i & 63;
        s_v[t][j] = vv[((c * TC + t) * B_DIM + b) * 64 + j];
    }

    // chunk-local multiply-scan of clamped alpha; w_raw = k * localprod
    const int tq = tid >> 6;     // 0..7, owns 4 consecutive timesteps
    const int n  = tid & 63;
    const int gbase = ((c * TC + tq * 4) * B_DIM + b) * 64 + n;  // +512 per t
    float p0, p1, p2, p3;
    {
        float r = fmaxf(alpha[gbase        ], EPSV); p0 = r;
        r      *= fmaxf(alpha[gbase +  512 ], EPSV); p1 = r;
        r      *= fmaxf(alpha[gbase + 1024 ], EPSV); p2 = r;
        r      *= fmaxf(alpha[gbase + 1536 ], EPSV); p3 = r;
        s_tot[tq][n] = r;
    }
    __syncthreads();
    if (tid < 64) {                      // exclusive product across 8 groups
        float run = 1.f;
#pragma unroll
        for (int q = 0; q < 8; q++) { float x = s_tot[q][tid]; s_tot[q][tid] = run; run *= x; }
        gLogAgg[(c * B_DIM + b) * 64 + tid] = logf(run);
    }
    __syncthreads();
    {
        float off = s_tot[tq][n];        // exclusive group prefix (local only)
        float w0 = kk[gbase        ] * (p0 * off);
        float w1 = kk[gbase +  512 ] * (p1 * off);
        float w2 = kk[gbase + 1024 ] * (p2 * off);
        float w3 = kk[gbase + 1536 ] * (p3 * off);
        s_w[(tq * 4 + 0) * 64 + n] = w0;  gWraw[gbase        ] = w0;
        s_w[(tq * 4 + 1) * 64 + n] = w1;  gWraw[gbase +  512 ] = w1;
        s_w[(tq * 4 + 2) * 64 + n] = w2;  gWraw[gbase + 1024 ] = w2;
        s_w[(tq * 4 + 3) * 64 + n] = w3;  gWraw[gbase + 1536 ] = w3;
    }
    __syncthreads();

    // unscaled chunk outer sums (full d: two rows per thread)
    const int d  = tid >> 4;     // 0..31
    const int n4 = tid & 15;
    float4 a0 = make_float4(0.f, 0.f, 0.f, 0.f), a1 = a0;
#pragma unroll
    for (int t = 0; t < TC; t++) {
        float v0 = s_v[t][d], v1 = s_v[t][d + 32];
        float4 w = s_w4[t][n4];
        a0.x += v0 * w.x; a0.y += v0 * w.y; a0.z += v0 * w.z; a0.w += v0 * w.w;
        a1.x += v1 * w.x; a1.y += v1 * w.y; a1.z += v1 * w.z; a1.w += v1 * w.w;
    }
    int base = (c * B_DIM + b) * 1024;
    gCraw[base + d * 16 + n4]        = a0;
    gCraw[base + (d + 32) * 16 + n4] = a1;
}

// ---------------------------------------------------------------------------
// K2: writer in R1's shape. grid (CH, B) = 256 blocks, 1024 threads, full d.
// Shuffle-scan scale table, fused w-scaling, MLP prefix reads, stream.
// ---------------------------------------------------------------------------
__global__ void __launch_bounds__(1024, 2)
k_stream(const float* __restrict__ vv, float4* __restrict__ out) {
    const int c = blockIdx.x, b = blockIdx.y;
    const int tid = threadIdx.x;

    __shared__ float  s_v[TC][64];       // 8 KB
    __shared__ float4 s_w4[TC][16];      // 8 KB
    __shared__ float4 s_sc4[CH][16];     // 8 KB scale table (cc, n)
    float* s_w  = (float*)s_w4;
    float* s_sc = (float*)s_sc4;

    // 1) v tile loads in flight first
    for (int i = tid; i < TC * 64; i += 1024) {
        int t = i >> 6, j = i & 63;
        s_v[t][j] = vv[((c * TC + t) * B_DIM + b) * 64 + j];
    }

    // 2) scale table via warp shuffle scan: warp -> n, lane -> cc. Two passes.
    {
        const int lane = tid & 31;       // cc
        const int wid  = tid >> 5;       // 0..31
#pragma unroll
        for (int p = 0; p < 2; p++) {
            int nn = wid + p * 32;
            float a = __ldg(&gLogAgg[(lane * B_DIM + b) * 64 + nn]);
            float incl = a;
#pragma unroll
            for (int o = 1; o < 32; o <<= 1) {
                float x = __shfl_up_sync(0xFFFFFFFFu, incl, o);
                if (lane >= o) incl += x;
            }
            float excl = __shfl_up_sync(0xFFFFFFFFu, incl, 1);
            if (lane == 0) excl = 0.f;
            float tot = __shfl_sync(0xFFFFFFFFu, incl, 31);
            s_sc[lane * 64 + nn] = expf(excl) / (expf(tot) + EPSV);
        }
    }
    __syncthreads();

    // 3) w load fused with scaling (scale for own chunk c)
    for (int i = tid; i < TC * 64; i += 1024) {
        int t = i >> 6, j = i & 63;
        s_w[i] = gWraw[((c * TC + t) * B_DIM + b) * 64 + j] * s_sc[c * 64 + j];
    }

    // 4) exclusive prefix: acc = sum_{cc<c} scale_cc (.) Craw_cc (MLP L2 reads)
    const int d  = tid >> 4;     // 0..63
    const int n4 = tid & 15;
    float4 acc = make_float4(0.f, 0.f, 0.f, 0.f);
    for (int cc = 0; cc < c; cc++) {
        float4 x  = __ldg(&gCraw[(cc * B_DIM + b) * 1024 + tid]);
        float4 sc = s_sc4[cc][n4];
        acc.x += sc.x * x.x; acc.y += sc.y * x.y;
        acc.z += sc.z * x.z; acc.w += sc.w * x.w;
    }
    __syncthreads();

    // 5) stream 32 timesteps (512 KB per block), contiguous 16 KB per t
#pragma unroll
    for (int t = 0; t < TC; t++) {
        float  vt = s_v[t][d];
        float4 wt = s_w4[t][n4];
        acc.x += vt * wt.x;
        acc.y += vt * wt.y;
        acc.z += vt * wt.z;
        acc.w += vt * wt.w;
        out[((c * TC + t) * B_DIM + b) * 1024 + tid] = acc;
    }
}

// ---------------------------------------------------------------------------
extern "C" void kernel_launch(void* const* d_in, const int* in_sizes, int n_in,
                              void* d_out, int out_size) {
    (void)in_sizes; (void)n_in; (void)out_size;
    const float* v     = (const float*)d_in[0];
    const float* k     = (const float*)d_in[1];
    const float* alpha = (const float*)d_in[2];
    float4* out = (float4*)d_out;

    k_chunk<<<dim3(CH, B_DIM), 512>>>(v, k, alpha);
    k_stream<<<dim3(CH, B_DIM), 1024>>>(v, out);
}

// round 13
// speedup vs baseline: 1.0065x; 1.0065x over previous
#include <cuda_runtime.h>
#include <cuda_bf16.h>

// Shapes fixed by problem: T=1024, B=8, D=64, N=64
#define T_DIM 1024
#define B_DIM 8
#define CH    32                   // K1 chunks over T
#define TC    (T_DIM / CH)         // 32 timesteps per K1 chunk
#define SC    16                   // K2 super-chunks
#define TS    (T_DIM / SC)         // 64 timesteps per K2 block
#define EPSV  1e-8f

// Scratch (device globals, allocation-free)
__device__ float  gLogAgg[CH * B_DIM * 64];  // log of per-chunk alpha product
__device__ float  gWraw[T_DIM * B_DIM * 64]; // k * chunk-local cumprod (2 MB)
__device__ float4 gCraw[CH * B_DIM * 1024];  // unscaled chunk outer sums (4 MB)

// ---------------------------------------------------------------------------
// K1: per (c,b): chunk-local multiply-scan -> w_raw, chunk outer sums -> gCraw,
//     chunk log product -> gLogAgg. No cross-chunk dependencies.
// grid (CH,B), 512 threads.
// ---------------------------------------------------------------------------
__global__ void __launch_bounds__(512)
k_chunk(const float* __restrict__ vv,
        const float* __restrict__ kk,
        const float* __restrict__ alpha) {
    const int c = blockIdx.x, b = blockIdx.y;
    const int tid = threadIdx.x;

    __shared__ float  s_v[TC][64];
    __shared__ float4 s_w4[TC][16];
    __shared__ float  s_tot[8][64];
    float* s_w = (float*)s_w4;

    // v tile load (coalesced)
    for (int i = tid; i < TC * 64; i += 512) {
        int t = i >> 6, j = i & 63;
        s_v[t][j] = vv[((c * TC + t) * B_DIM + b) * 64 + j];
    }

    // chunk-local multiply-scan of clamped alpha; w_raw = k * localprod
    const int tq = tid >> 6;     // 0..7, owns 4 consecutive timesteps
    const int n  = tid & 63;
    const int gbase = ((c * TC + tq * 4) * B_DIM + b) * 64 + n;  // +512 per t
    float p0, p1, p2, p3;
    {
        float r = fmaxf(alpha[gbase        ], EPSV); p0 = r;
        r      *= fmaxf(alpha[gbase +  512 ], EPSV); p1 = r;
        r      *= fmaxf(alpha[gbase + 1024 ], EPSV); p2 = r;
        r      *= fmaxf(alpha[gbase + 1536 ], EPSV); p3 = r;
        s_tot[tq][n] = r;
    }
    __syncthreads();
    if (tid < 64) {                      // exclusive product across 8 groups
        float run = 1.f;
#pragma unroll
        for (int q = 0; q < 8; q++) { float x = s_tot[q][tid]; s_tot[q][tid] = run; run *= x; }
        gLogAgg[(c * B_DIM + b) * 64 + tid] = logf(run);
    }
    __syncthreads();
    {
        float off = s_tot[tq][n];        // exclusive group prefix (local only)
        float w0 = kk[gbase        ] * (p0 * off);
        float w1 = kk[gbase +  512 ] * (p1 * off);
        float w2 = kk[gbase + 1024 ] * (p2 * off);
        float w3 = kk[gbase + 1536 ] * (p3 * off);
        s_w[(tq * 4 + 0) * 64 + n] = w0;  gWraw[gbase        ] = w0;
        s_w[(tq * 4 + 1) * 64 + n] = w1;  gWraw[gbase +  512 ] = w1;
        s_w[(tq * 4 + 2) * 64 + n] = w2;  gWraw[gbase + 1024 ] = w2;
        s_w[(tq * 4 + 3) * 64 + n] = w3;  gWraw[gbase + 1536 ] = w3;
    }
    __syncthreads();

    // unscaled chunk outer sums (full d: two rows per thread)
    const int d  = tid >> 4;     // 0..31
    const int n4 = tid & 15;
    float4 a0 = make_float4(0.f, 0.f, 0.f, 0.f), a1 = a0;
#pragma unroll
    for (int t = 0; t < TC; t++) {
        float v0 = s_v[t][d], v1 = s_v[t][d + 32];
        float4 w = s_w4[t][n4];
        a0.x += v0 * w.x; a0.y += v0 * w.y; a0.z += v0 * w.z; a0.w += v0 * w.w;
        a1.x += v1 * w.x; a1.y += v1 * w.y; a1.z += v1 * w.z; a1.w += v1 * w.w;
    }
    int base = (c * B_DIM + b) * 1024;
    gCraw[base + d * 16 + n4]        = a0;
    gCraw[base + (d + 32) * 16 + n4] = a1;
}

// ---------------------------------------------------------------------------
// K2: scale table (shuffle scan) + prefix from gCraw + stream 64 timesteps.
// grid (SC, B, 2) = 256 blocks, 512 threads. h selects d-half.
// ---------------------------------------------------------------------------
__global__ void __launch_bounds__(512)
k_stream(const float* __restrict__ vv, float4* __restrict__ out) {
    const int c2 = blockIdx.x, b = blockIdx.y, h = blockIdx.z;
    const int tid = threadIdx.x;

    __shared__ float  s_v[TS][32];       // 8 KB
    __shared__ float4 s_w4[TS][16];      // 16 KB
    __shared__ float4 s_sc4[CH][16];     // 8 KB scale table (cc, n)
    float* s_w  = (float*)s_w4;
    float* s_sc = (float*)s_sc4;

    const int t0 = c2 * TS;

    // issue tile loads first (latency overlap with scale table)
    for (int i = tid; i < TS * 32; i += 512) {
        int t = i >> 5, j = i & 31;
        s_v[t][j] = vv[((t0 + t) * B_DIM + b) * 64 + h * 32 + j];
    }
    for (int i = tid; i < TS * 64; i += 512) {
        int t = i >> 6, j = i & 63;
        s_w[i] = gWraw[((t0 + t) * B_DIM + b) * 64 + j];
    }

    // scale table via warp shuffle scan: warp -> n, lane -> cc. 4 passes.
    {
        const int lane = tid & 31;       // cc
        const int wrp  = tid >> 5;       // 0..15
#pragma unroll
        for (int p = 0; p < 4; p++) {
            int nn = wrp + p * 16;
            float incl = __ldg(&gLogAgg[(lane * B_DIM + b) * 64 + nn]);
#pragma unroll
            for (int o = 1; o < 32; o <<= 1) {
                float x = __shfl_up_sync(0xFFFFFFFFu, incl, o);
                if (lane >= o) incl += x;
            }
            float excl = __shfl_up_sync(0xFFFFFFFFu, incl, 1);
            if (lane == 0) excl = 0.f;
            float tot = __shfl_sync(0xFFFFFFFFu, incl, 31);
            s_sc[lane * 64 + nn] = expf(excl) / (expf(tot) + EPSV);
        }
    }
    __syncthreads();

    // scale w in smem: first 32 t use chunk 2*c2, next 32 use 2*c2+1
    for (int i = tid; i < TS * 64; i += 512) {
        int cc = c2 * 2 + ((i >> 6) >> 5);
        s_w[i] *= s_sc[cc * 64 + (i & 63)];
    }
    __syncthreads();

    const int dl = tid >> 4;     // 0..31 local d row
    const int n4 = tid & 15;
    const int lane = (h * 32 + dl) * 16 + n4;

    // exclusive prefix: sum over K1 chunks before this super-chunk (MLP reads)
    float4 acc = make_float4(0.f, 0.f, 0.f, 0.f);
#pragma unroll 4
    for (int cc = 0; cc < c2 * 2; cc++) {
        float4 x  = __ldg(&gCraw[(cc * B_DIM + b) * 1024 + lane]);
        float4 sc = s_sc4[cc][n4];
        acc.x += sc.x * x.x; acc.y += sc.y * x.y;
        acc.z += sc.z * x.z; acc.w += sc.w * x.w;
    }

    // stream 64 timesteps (512 KB per block)
#pragma unroll
    for (int t = 0; t < TS; t++) {
        float  vt = s_v[t][dl];
        float4 wt = s_w4[t][n4];
        acc.x += vt * wt.x;
        acc.y += vt * wt.y;
        acc.z += vt * wt.z;
        acc.w += vt * wt.w;
        out[((t0 + t) * B_DIM + b) * 1024 + lane] = acc;
    }
}

// ---------------------------------------------------------------------------
extern "C" void kernel_launch(void* const* d_in, const int* in_sizes, int n_in,
                              void* d_out, int out_size) {
    (void)in_sizes; (void)n_in; (void)out_size;
    const float* v     = (const float*)d_in[0];
    const float* k     = (const float*)d_in[1];
    const float* alpha = (const float*)d_in[2];
    float4* out = (float4*)d_out;

    k_chunk<<<dim3(CH, B_DIM), 512>>>(v, k, alpha);
    k_stream<<<dim3(SC, B_DIM, 2), 512>>>(v, out);
}

// round 14
// speedup vs baseline: 1.1479x; 1.1405x over previous
#include <cuda_runtime.h>
#include <cuda_bf16.h>

// Shapes fixed by problem: T=1024, B=8, D=64, N=64
#define T_DIM 1024
#define B_DIM 8
#define CH    32                   // chunks over T
#define TC    (T_DIM / CH)         // 32 timesteps per chunk
#define EPSV  1e-8f

// Scratch (device globals, allocation-free)
__device__ float  gLogAgg[CH * B_DIM * 64];  // log of per-chunk alpha product
__device__ float  gWraw[T_DIM * B_DIM * 64]; // k * chunk-local cumprod (2 MB)
__device__ float4 gCraw[CH * B_DIM * 1024];  // unscaled chunk outer sums (4 MB)
__device__ float4 gP[CH * B_DIM * 1024];     // scaled exclusive prefix tiles (4 MB)

// ---------------------------------------------------------------------------
// K1: per (c,b): chunk-local multiply-scan -> w_raw, chunk outer sums -> gCraw,
//     chunk log product -> gLogAgg. No cross-chunk dependencies.
// grid (CH,B), 512 threads.
// ---------------------------------------------------------------------------
__global__ void __launch_bounds__(512)
k_chunk(const float* __restrict__ vv,
        const float* __restrict__ kk,
        const float* __restrict__ alpha) {
    const int c = blockIdx.x, b = blockIdx.y;
    const int tid = threadIdx.x;

    __shared__ float  s_v[TC][64];
    __shared__ float4 s_w4[TC][16];
    __shared__ float  s_tot[8][64];
    float* s_w = (float*)s_w4;

    // v tile load (coalesced)
    for (int i = tid; i < TC * 64; i += 512) {
        int t = i >> 6, j = i & 63;
        s_v[t][j] = vv[((c * TC + t) * B_DIM + b) * 64 + j];
    }

    // chunk-local multiply-scan of clamped alpha; w_raw = k * localprod
    const int tq = tid >> 6;     // 0..7, owns 4 consecutive timesteps
    const int n  = tid & 63;
    const int gbase = ((c * TC + tq * 4) * B_DIM + b) * 64 + n;  // +512 per t
    float p0, p1, p2, p3;
    {
        float r = fmaxf(alpha[gbase        ], EPSV); p0 = r;
        r      *= fmaxf(alpha[gbase +  512 ], EPSV); p1 = r;
        r      *= fmaxf(alpha[gbase + 1024 ], EPSV); p2 = r;
        r      *= fmaxf(alpha[gbase + 1536 ], EPSV); p3 = r;
        s_tot[tq][n] = r;
    }
    __syncthreads();
    if (tid < 64) {                      // exclusive product across 8 groups
        float run = 1.f;
#pragma unroll
        for (int q = 0; q < 8; q++) { float x = s_tot[q][tid]; s_tot[q][tid] = run; run *= x; }
        gLogAgg[(c * B_DIM + b) * 64 + tid] = logf(run);
    }
    __syncthreads();
    {
        float off = s_tot[tq][n];        // exclusive group prefix (local only)
        float w0 = kk[gbase        ] * (p0 * off);
        float w1 = kk[gbase +  512 ] * (p1 * off);
        float w2 = kk[gbase + 1024 ] * (p2 * off);
        float w3 = kk[gbase + 1536 ] * (p3 * off);
        s_w[(tq * 4 + 0) * 64 + n] = w0;  gWraw[gbase        ] = w0;
        s_w[(tq * 4 + 1) * 64 + n] = w1;  gWraw[gbase +  512 ] = w1;
        s_w[(tq * 4 + 2) * 64 + n] = w2;  gWraw[gbase + 1024 ] = w2;
        s_w[(tq * 4 + 3) * 64 + n] = w3;  gWraw[gbase + 1536 ] = w3;
    }
    __syncthreads();

    // unscaled chunk outer sums (full d: two rows per thread)
    const int d  = tid >> 4;     // 0..31
    const int n4 = tid & 15;
    float4 a0 = make_float4(0.f, 0.f, 0.f, 0.f), a1 = a0;
#pragma unroll
    for (int t = 0; t < TC; t++) {
        float v0 = s_v[t][d], v1 = s_v[t][d + 32];
        float4 w = s_w4[t][n4];
        a0.x += v0 * w.x; a0.y += v0 * w.y; a0.z += v0 * w.z; a0.w += v0 * w.w;
        a1.x += v1 * w.x; a1.y += v1 * w.y; a1.z += v1 * w.z; a1.w += v1 * w.w;
    }
    int base = (c * B_DIM + b) * 1024;
    gCraw[base + d * 16 + n4]        = a0;
    gCraw[base + (d + 32) * 16 + n4] = a1;
}

// ---------------------------------------------------------------------------
// K2: scaled exclusive prefix tiles: gP[c] = sum_{cc<c} scale_cc (.) Craw_cc.
// grid (32 slices, B) = 256 blocks, 256 threads. Slice = 32 float4 lanes.
// ---------------------------------------------------------------------------
__global__ void __launch_bounds__(256)
k_prep() {
    const int s = blockIdx.x;            // 0..31: float4-lane slice
    const int b = blockIdx.y;
    const int tid = threadIdx.x;

    __shared__ float  s_sc[CH][64];      // 8 KB scale table
    __shared__ float4 s_c[CH][32];       // 16 KB Craw slice

    // load Craw slice (coalesced, MLP)
    for (int i = tid; i < CH * 32; i += 256) {
        int cc = i >> 5, l = i & 31;
        s_c[cc][l] = gCraw[(cc * B_DIM + b) * 1024 + s * 32 + l];
    }

    // scale table: coalesced aggregate loads (tid<64 consecutive), reg scan
    if (tid < 64) {
        float a[CH];
#pragma unroll
        for (int cc = 0; cc < CH; cc++)
            a[cc] = __ldg(&gLogAgg[(cc * B_DIM + b) * 64 + tid]);
        float run = 0.f;
#pragma unroll
        for (int cc = 0; cc < CH; cc++) { s_sc[cc][tid] = expf(run); run += a[cc]; }
        float inv = 1.f / (expf(run) + EPSV);
#pragma unroll
        for (int cc = 0; cc < CH; cc++) s_sc[cc][tid] *= inv;
    }
    __syncthreads();

    // serial scaled scan down the chunk axis; one float column per thread
    if (tid < 128) {
        const int l = tid >> 2, comp = tid & 3;
        const int n = ((s * 32 + l) & 15) * 4 + comp;    // lane -> n mapping
        float run = 0.f;
#pragma unroll
        for (int cc = 0; cc < CH; cc++) {
            float* p = (float*)&s_c[cc][l] + comp;
            float x = *p;
            *p = run;
            run += s_sc[cc][n] * x;
        }
    }
    __syncthreads();

    // store exclusive prefix slice (coalesced)
    for (int i = tid; i < CH * 32; i += 256) {
        int cc = i >> 5, l = i & 31;
        gP[(cc * B_DIM + b) * 1024 + s * 32 + l] = s_c[cc][l];
    }
}

// ---------------------------------------------------------------------------
// K3: pure writer (R1 shape). grid (CH,B), 1024 threads.
// Scale row fused into w load; gP preloaded; contiguous 16 KB stores per t.
// ---------------------------------------------------------------------------
__global__ void __launch_bounds__(1024, 2)
k_main(const float* __restrict__ vv, float4* __restrict__ out) {
    const int c = blockIdx.x, b = blockIdx.y;
    const int tid = threadIdx.x;

    __shared__ float  s_v[TC][64];       // 8 KB
    __shared__ float4 s_w4[TC][16];      // 8 KB
    __shared__ float  s_scale[64];
    float* s_w = (float*)s_w4;

    // v tile loads in flight first
    for (int i = tid; i < TC * 64; i += 1024) {
        int t = i >> 6, j = i & 63;
        s_v[t][j] = vv[((c * TC + t) * B_DIM + b) * 64 + j];
    }

    // scale row for this chunk: coalesced MLP sums + 2 expf
    if (tid < 64) {
        float pre = 0.f, run = 0.f;
        for (int cc = 0; cc < CH; cc++) {
            if (cc == c) pre = run;
            run += __ldg(&gLogAgg[(cc * B_DIM + b) * 64 + tid]);
        }
        s_scale[tid] = expf(pre) / (expf(run) + EPSV);
    }
    __syncthreads();

    // w load fused with scaling
    for (int i = tid; i < TC * 64; i += 1024) {
        int t = i >> 6, j = i & 63;
        s_w[i] = gWraw[((c * TC + t) * B_DIM + b) * 64 + j] * s_scale[j];
    }

    // prefix preload (private, no sync needed before use)
    float4 acc = gP[(c * B_DIM + b) * 1024 + tid];
    __syncthreads();

    const int d  = tid >> 4;
    const int n4 = tid & 15;

    // stream 32 timesteps; each t is one contiguous 16 KB row
#pragma unroll
    for (int t = 0; t < TC; t++) {
        float  vt = s_v[t][d];
        float4 wt = s_w4[t][n4];
        acc.x += vt * wt.x;
        acc.y += vt * wt.y;
        acc.z += vt * wt.z;
        acc.w += vt * wt.w;
        out[((c * TC + t) * B_DIM + b) * 1024 + tid] = acc;
    }
}

// ---------------------------------------------------------------------------
extern "C" void kernel_launch(void* const* d_in, const int* in_sizes, int n_in,
                              void* d_out, int out_size) {
    (void)in_sizes; (void)n_in; (void)out_size;
    const float* v     = (const float*)d_in[0];
    const float* k     = (const float*)d_in[1];
    const float* alpha = (const float*)d_in[2];
    float4* out = (float4*)d_out;

    k_chunk<<<dim3(CH, B_DIM), 512>>>(v, k, alpha);
    k_prep<<<dim3(32, B_DIM), 256>>>();
    k_main<<<dim3(CH, B_DIM), 1024>>>(v, out);
}

// round 15
// speedup vs baseline: 1.2662x; 1.1031x over previous
#include <cuda_runtime.h>
#include <cuda_bf16.h>

// Shapes fixed by problem: T=1024, B=8, D=64, N=64
#define T_DIM 1024
#define B_DIM 8
#define CH    32                   // chunks over T
#define TC    (T_DIM / CH)         // 32 timesteps per chunk
#define EPSV  1e-8f

// Scratch (device globals, allocation-free). float4 types guarantee alignment.
__device__ float  gLogAgg[CH * B_DIM * 64];  // log of per-chunk alpha product
__device__ float4 gWraw4[T_DIM * B_DIM * 16];// k * chunk-local cumprod (2 MB)
__device__ float4 gCraw[CH * B_DIM * 1024];  // unscaled chunk outer sums (4 MB)
__device__ float4 gP[CH * B_DIM * 1024];     // scaled exclusive prefix tiles (4 MB)
__device__ float  gScale[CH * B_DIM * 64];   // decay scale per (chunk, b, n)

// ---------------------------------------------------------------------------
// K1: per (c,b): chunk-local multiply-scan -> gWraw4, chunk outer sums -> gCraw,
//     chunk log product -> gLogAgg. All global traffic float4.
// grid (CH,B), 512 threads.
// ---------------------------------------------------------------------------
__global__ void __launch_bounds__(512)
k_chunk(const float4* __restrict__ v4,
        const float4* __restrict__ k4,
        const float4* __restrict__ a4) {
    const int c = blockIdx.x, b = blockIdx.y;
    const int tid = threadIdx.x;

    __shared__ float s_v[TC][64];        // 8 KB
    __shared__ float s_w[TC][64];        // 8 KB (scan in place)
    __shared__ float s_tot[8][64];       // 2 KB
    float4* s_v4   = (float4*)s_v;
    float4* s_w4   = (float4*)s_w;
    float4* s_tot4 = (float4*)s_tot;

    // one float4 per thread: tile = 512 float4s
    {
        int t = tid >> 4, j4 = tid & 15;
        int g = ((c * TC + t) * B_DIM + b) * 16 + j4;
        s_v4[tid] = v4[g];
        float4 a = a4[g];
        a.x = fmaxf(a.x, EPSV); a.y = fmaxf(a.y, EPSV);
        a.z = fmaxf(a.z, EPSV); a.w = fmaxf(a.w, EPSV);
        s_w4[tid] = a;
    }
    __syncthreads();

    // in-place inclusive multiply-scan within 8 groups of 4 t (float4 columns)
    if (tid < 128) {
        int tq = tid >> 4, q = tid & 15;
        float4 r = make_float4(1.f, 1.f, 1.f, 1.f);
#pragma unroll
        for (int i = 0; i < 4; i++) {
            int t = tq * 4 + i;
            float4 x = s_w4[t * 16 + q];
            r.x *= x.x; r.y *= x.y; r.z *= x.z; r.w *= x.w;
            s_w4[t * 16 + q] = r;
        }
        s_tot4[tq * 16 + q] = r;
    }
    __syncthreads();
    if (tid < 64) {                      // exclusive product across 8 groups
        float run = 1.f;
#pragma unroll
        for (int qq = 0; qq < 8; qq++) { float x = s_tot[qq][tid]; s_tot[qq][tid] = run; run *= x; }
        gLogAgg[(c * B_DIM + b) * 64 + tid] = logf(run);
    }
    __syncthreads();

    // finalize: w = k * (localprod * groupprefix); store gWraw4 (float4)
    if (tid < 128) {
        int tq = tid >> 4, q = tid & 15;
        float4 off = s_tot4[tq * 16 + q];
#pragma unroll
        for (int i = 0; i < 4; i++) {
            int t = tq * 4 + i;
            int g = ((c * TC + t) * B_DIM + b) * 16 + q;
            float4 kx = __ldg(&k4[g]);
            float4 w  = s_w4[t * 16 + q];
            w.x = kx.x * (w.x * off.x);
            w.y = kx.y * (w.y * off.y);
            w.z = kx.z * (w.z * off.z);
            w.w = kx.w * (w.w * off.w);
            s_w4[t * 16 + q] = w;
            gWraw4[g] = w;
        }
    }
    __syncthreads();

    // unscaled chunk outer sums (full d: two rows per thread)
    const int d  = tid >> 4;     // 0..31
    const int n4 = tid & 15;
    float4 a0 = make_float4(0.f, 0.f, 0.f, 0.f), a1 = a0;
#pragma unroll
    for (int t = 0; t < TC; t++) {
        float v0 = s_v[t][d], v1 = s_v[t][d + 32];
        float4 w = s_w4[t * 16 + n4];
        a0.x += v0 * w.x; a0.y += v0 * w.y; a0.z += v0 * w.z; a0.w += v0 * w.w;
        a1.x += v1 * w.x; a1.y += v1 * w.y; a1.z += v1 * w.z; a1.w += v1 * w.w;
    }
    int base = (c * B_DIM + b) * 1024;
    gCraw[base + d * 16 + n4]        = a0;
    gCraw[base + (d + 32) * 16 + n4] = a1;
}

// ---------------------------------------------------------------------------
// K2: scaled exclusive prefix tiles gP[c] = sum_{cc<c} scale_cc (.) Craw_cc,
//     and (s==0 blocks) persist the scale table to gScale.
// grid (32 slices, B) = 256 blocks, 256 threads. Slice = 32 float4 lanes.
// ---------------------------------------------------------------------------
__global__ void __launch_bounds__(256)
k_prep() {
    const int s = blockIdx.x;            // 0..31: float4-lane slice
    const int b = blockIdx.y;
    const int tid = threadIdx.x;

    __shared__ float  s_sc[CH][64];      // 8 KB scale table
    __shared__ float4 s_c[CH][32];       // 16 KB Craw slice

    // load Craw slice (coalesced, MLP)
    for (int i = tid; i < CH * 32; i += 256) {
        int cc = i >> 5, l = i & 31;
        s_c[cc][l] = gCraw[(cc * B_DIM + b) * 1024 + s * 32 + l];
    }

    // scale table: coalesced aggregate loads (tid<64 consecutive), reg scan
    if (tid < 64) {
        float a[CH];
#pragma unroll
        for (int cc = 0; cc < CH; cc++)
            a[cc] = __ldg(&gLogAgg[(cc * B_DIM + b) * 64 + tid]);
        float run = 0.f;
#pragma unroll
        for (int cc = 0; cc < CH; cc++) { s_sc[cc][tid] = expf(run); run += a[cc]; }
        float inv = 1.f / (expf(run) + EPSV);
#pragma unroll
        for (int cc = 0; cc < CH; cc++) s_sc[cc][tid] *= inv;
        if (s == 0) {                    // persist for k_main
#pragma unroll
            for (int cc = 0; cc < CH; cc++)
                gScale[(cc * B_DIM + b) * 64 + tid] = s_sc[cc][tid];
        }
    }
    __syncthreads();

    // serial scaled scan down the chunk axis; one float column per thread
    if (tid < 128) {
        const int l = tid >> 2, comp = tid & 3;
        const int n = ((s * 32 + l) & 15) * 4 + comp;    // lane -> n mapping
        float run = 0.f;
#pragma unroll
        for (int cc = 0; cc < CH; cc++) {
            float* p = (float*)&s_c[cc][l] + comp;
            float x = *p;
            *p = run;
            run += s_sc[cc][n] * x;
        }
    }
    __syncthreads();

    // store exclusive prefix slice (coalesced)
    for (int i = tid; i < CH * 32; i += 256) {
        int cc = i >> 5, l = i & 31;
        gP[(cc * B_DIM + b) * 1024 + s * 32 + l] = s_c[cc][l];
    }
}

// ---------------------------------------------------------------------------
// K3: pure writer. grid (CH,B), 1024 threads. All float4 traffic, 2 syncs.
// ---------------------------------------------------------------------------
__global__ void __launch_bounds__(1024, 2)
k_main(const float4* __restrict__ v4, float4* __restrict__ out) {
    const int c = blockIdx.x, b = blockIdx.y;
    const int tid = threadIdx.x;

    __shared__ float  s_v[TC][64];       // 8 KB
    __shared__ float4 s_w4[TC][16];      // 8 KB
    __shared__ float  s_scale[64];

    // v tile (warps 0-15) and scale row (warps 16-17) load concurrently
    if (tid < 512) {
        int t = tid >> 4, j4 = tid & 15;
        ((float4*)s_v)[tid] = v4[((c * TC + t) * B_DIM + b) * 16 + j4];
    } else if (tid < 576) {
        s_scale[tid - 512] = gScale[(c * B_DIM + b) * 64 + (tid - 512)];
    }
    // prefix preload (private)
    float4 acc = gP[(c * B_DIM + b) * 1024 + tid];
    __syncthreads();

    // w load fused with scaling (float4)
    if (tid < 512) {
        int t = tid >> 4, j4 = tid & 15;
        float4 w  = gWraw4[((c * TC + t) * B_DIM + b) * 16 + j4];
        float4 sc = ((float4*)s_scale)[j4];
        w.x *= sc.x; w.y *= sc.y; w.z *= sc.z; w.w *= sc.w;
        s_w4[t][j4] = w;
    }
    __syncthreads();

    const int d  = tid >> 4;
    const int n4 = tid & 15;

    // stream 32 timesteps; each t is one contiguous 16 KB row
#pragma unroll
    for (int t = 0; t < TC; t++) {
        float  vt = s_v[t][d];
        float4 wt = s_w4[t][n4];
        acc.x += vt * wt.x;
        acc.y += vt * wt.y;
        acc.z += vt * wt.z;
        acc.w += vt * wt.w;
        out[((c * TC + t) * B_DIM + b) * 1024 + tid] = acc;
    }
}

// ---------------------------------------------------------------------------
extern "C" void kernel_launch(void* const* d_in, const int* in_sizes, int n_in,
                              void* d_out, int out_size) {
    (void)in_sizes; (void)n_in; (void)out_size;
    const float4* v     = (const float4*)d_in[0];
    const float4* k     = (const float4*)d_in[1];
    const float4* alpha = (const float4*)d_in[2];
    float4* out = (float4*)d_out;

    k_chunk<<<dim3(CH, B_DIM), 512>>>(v, k, alpha);
    k_prep<<<dim3(32, B_DIM), 256>>>();
    k_main<<<dim3(CH, B_DIM), 1024>>>(v, out);
}

// round 16
// speedup vs baseline: 1.4130x; 1.1159x over previous
#include <cuda_runtime.h>
#include <cuda_bf16.h>

// Shapes fixed by problem: T=1024, B=8, D=64, N=64
#define T_DIM 1024
#define B_DIM 8
#define CH    32                   // chunks over T
#define TC    (T_DIM / CH)         // 32 timesteps per chunk
#define EPSV  1e-8f

// Scratch (device globals, allocation-free). float4 types guarantee alignment.
__device__ float  gLogAgg[CH * B_DIM * 64];  // log of per-chunk alpha product
__device__ float4 gWraw4[T_DIM * B_DIM * 16];// k * chunk-local cumprod (2 MB)
__device__ float4 gCraw[CH * B_DIM * 1024];  // unscaled chunk outer sums (4 MB)
__device__ float4 gP[CH * B_DIM * 1024];     // scaled exclusive prefix tiles (4 MB)
__device__ float  gScale[CH * B_DIM * 64];   // decay scale per (chunk, b, n)

// ---------------------------------------------------------------------------
// K1: per (c,b): chunk-local multiply-scan -> gWraw4, chunk outer sums -> gCraw,
//     chunk log product -> gLogAgg. 4x4 register tiles, t-split halves.
// grid (CH,B), 512 threads.
// ---------------------------------------------------------------------------
__global__ void __launch_bounds__(512)
k_chunk(const float4* __restrict__ v4,
        const float4* __restrict__ k4,
        const float4* __restrict__ a4) {
    const int c = blockIdx.x, b = blockIdx.y;
    const int tid = threadIdx.x;

    __shared__ float4 s_v4[TC * 16];     // 8 KB  v tile
    __shared__ float4 s_w4[TC * 16];     // 8 KB  alpha -> scan -> w
    __shared__ float  s_tot[8][64];      // 2 KB
    float4* s_tot4 = (float4*)s_tot;

    // one float4 per thread: tile = 512 float4s
    {
        int t = tid >> 4, j4 = tid & 15;
        int g = ((c * TC + t) * B_DIM + b) * 16 + j4;
        s_v4[tid] = v4[g];
        float4 a = a4[g];
        a.x = fmaxf(a.x, EPSV); a.y = fmaxf(a.y, EPSV);
        a.z = fmaxf(a.z, EPSV); a.w = fmaxf(a.w, EPSV);
        s_w4[tid] = a;
    }
    __syncthreads();

    // in-place inclusive multiply-scan within 8 groups of 4 t (float4 columns)
    if (tid < 128) {
        int tq = tid >> 4, q = tid & 15;
        float4 r = make_float4(1.f, 1.f, 1.f, 1.f);
#pragma unroll
        for (int i = 0; i < 4; i++) {
            int t = tq * 4 + i;
            float4 x = s_w4[t * 16 + q];
            r.x *= x.x; r.y *= x.y; r.z *= x.z; r.w *= x.w;
            s_w4[t * 16 + q] = r;
        }
        s_tot4[tq * 16 + q] = r;
    }
    __syncthreads();
    if (tid < 64) {                      // exclusive product across 8 groups
        float run = 1.f;
#pragma unroll
        for (int qq = 0; qq < 8; qq++) { float x = s_tot[qq][tid]; s_tot[qq][tid] = run; run *= x; }
        gLogAgg[(c * B_DIM + b) * 64 + tid] = logf(run);
    }
    __syncthreads();

    // finalize on ALL 512 threads: w = k * (localprod * groupprefix)
    {
        int t = tid >> 4, j4 = tid & 15;
        int g = ((c * TC + t) * B_DIM + b) * 16 + j4;
        float4 off = s_tot4[(t >> 2) * 16 + j4];
        float4 kx  = __ldg(&k4[g]);
        float4 w   = s_w4[tid];
        w.x = kx.x * (w.x * off.x);
        w.y = kx.y * (w.y * off.y);
        w.z = kx.z * (w.z * off.z);
        w.w = kx.w * (w.w * off.w);
        s_w4[tid] = w;
        gWraw4[g] = w;
    }
    __syncthreads();

    // outer sums: 4x4 register tiles; halves split t. 16 FMA per 32 B LDS.
    const int half = tid >> 8;           // 0 | 1
    const int idx  = tid & 255;
    const int dq   = idx >> 4;           // 0..15 -> d rows 4dq..4dq+3
    const int nq   = idx & 15;
    float4 a0 = make_float4(0.f,0.f,0.f,0.f), a1 = a0, a2 = a0, a3 = a0;
#pragma unroll
    for (int i = 0; i < 16; i++) {
        int t = half * 16 + i;
        float4 va = s_v4[t * 16 + dq];
        float4 w  = s_w4[t * 16 + nq];
        a0.x += va.x * w.x; a0.y += va.x * w.y; a0.z += va.x * w.z; a0.w += va.x * w.w;
        a1.x += va.y * w.x; a1.y += va.y * w.y; a1.z += va.y * w.z; a1.w += va.y * w.w;
        a2.x += va.z * w.x; a2.y += va.z * w.y; a2.z += va.z * w.z; a2.w += va.z * w.w;
        a3.x += va.w * w.x; a3.y += va.w * w.y; a3.z += va.w * w.z; a3.w += va.w * w.w;
    }
    __syncthreads();                     // v/w tiles now dead; reuse as scratch
    if (half == 1) {
        s_v4[idx * 2 + 0] = a0;  s_v4[idx * 2 + 1] = a1;
        s_w4[idx * 2 + 0] = a2;  s_w4[idx * 2 + 1] = a3;
    }
    __syncthreads();
    if (half == 0) {
        float4 x;
        x = s_v4[idx * 2 + 0]; a0.x += x.x; a0.y += x.y; a0.z += x.z; a0.w += x.w;
        x = s_v4[idx * 2 + 1]; a1.x += x.x; a1.y += x.y; a1.z += x.z; a1.w += x.w;
        x = s_w4[idx * 2 + 0]; a2.x += x.x; a2.y += x.y; a2.z += x.z; a2.w += x.w;
        x = s_w4[idx * 2 + 1]; a3.x += x.x; a3.y += x.y; a3.z += x.z; a3.w += x.w;
        int base = (c * B_DIM + b) * 1024 + nq;
        gCraw[base + (dq * 4 + 0) * 16] = a0;
        gCraw[base + (dq * 4 + 1) * 16] = a1;
        gCraw[base + (dq * 4 + 2) * 16] = a2;
        gCraw[base + (dq * 4 + 3) * 16] = a3;
    }
}

// ---------------------------------------------------------------------------
// K2: scaled exclusive prefix tiles gP[c] = sum_{cc<c} scale_cc (.) Craw_cc,
//     and (s==0 blocks) persist the scale table to gScale.
// grid (32 slices, B) = 256 blocks, 256 threads. Slice = 32 float4 lanes.
// ---------------------------------------------------------------------------
__global__ void __launch_bounds__(256)
k_prep() {
    const int s = blockIdx.x;            // 0..31: float4-lane slice
    const int b = blockIdx.y;
    const int tid = threadIdx.x;

    __shared__ float  s_sc[CH][64];      // 8 KB scale table
    __shared__ float4 s_c[CH][32];       // 16 KB Craw slice

    // load Craw slice (coalesced, MLP)
    for (int i = tid; i < CH * 32; i += 256) {
        int cc = i >> 5, l = i & 31;
        s_c[cc][l] = gCraw[(cc * B_DIM + b) * 1024 + s * 32 + l];
    }

    // scale table: coalesced aggregate loads (tid<64 consecutive), reg scan
    if (tid < 64) {
        float a[CH];
#pragma unroll
        for (int cc = 0; cc < CH; cc++)
            a[cc] = __ldg(&gLogAgg[(cc * B_DIM + b) * 64 + tid]);
        float run = 0.f;
#pragma unroll
        for (int cc = 0; cc < CH; cc++) { s_sc[cc][tid] = expf(run); run += a[cc]; }
        float inv = 1.f / (expf(run) + EPSV);
#pragma unroll
        for (int cc = 0; cc < CH; cc++) s_sc[cc][tid] *= inv;
        if (s == 0) {                    // persist for k_main
#pragma unroll
            for (int cc = 0; cc < CH; cc++)
                gScale[(cc * B_DIM + b) * 64 + tid] = s_sc[cc][tid];
        }
    }
    __syncthreads();

    // serial scaled scan down the chunk axis; one float column per thread
    if (tid < 128) {
        const int l = tid >> 2, comp = tid & 3;
        const int n = ((s * 32 + l) & 15) * 4 + comp;    // lane -> n mapping
        float run = 0.f;
#pragma unroll
        for (int cc = 0; cc < CH; cc++) {
            float* p = (float*)&s_c[cc][l] + comp;
            float x = *p;
            *p = run;
            run += s_sc[cc][n] * x;
        }
    }
    __syncthreads();

    // store exclusive prefix slice (coalesced)
    for (int i = tid; i < CH * 32; i += 256) {
        int cc = i >> 5, l = i & 31;
        gP[(cc * B_DIM + b) * 1024 + s * 32 + l] = s_c[cc][l];
    }
}

// ---------------------------------------------------------------------------
// K3: pure writer. grid (CH,B), 1024 threads. float4 + streaming cache hints.
// ---------------------------------------------------------------------------
__global__ void __launch_bounds__(1024, 2)
k_main(const float4* __restrict__ v4, float4* __restrict__ out) {
    const int c = blockIdx.x, b = blockIdx.y;
    const int tid = threadIdx.x;

    __shared__ float  s_v[TC][64];       // 8 KB
    __shared__ float4 s_w4[TC][16];      // 8 KB
    __shared__ float  s_scale[64];

    // v tile (warps 0-15) and scale row (warps 16-17) load concurrently
    if (tid < 512) {
        int t = tid >> 4, j4 = tid & 15;
        ((float4*)s_v)[tid] = v4[((c * TC + t) * B_DIM + b) * 16 + j4];
    } else if (tid < 576) {
        s_scale[tid - 512] = gScale[(c * B_DIM + b) * 64 + (tid - 512)];
    }
    // prefix preload (private, read-once)
    float4 acc = __ldcs(&gP[(c * B_DIM + b) * 1024 + tid]);
    __syncthreads();

    // w load fused with scaling (float4, read-once)
    if (tid < 512) {
        int t = tid >> 4, j4 = tid & 15;
        float4 w  = __ldcs(&gWraw4[((c * TC + t) * B_DIM + b) * 16 + j4]);
        float4 sc = ((float4*)s_scale)[j4];
        w.x *= sc.x; w.y *= sc.y; w.z *= sc.z; w.w *= sc.w;
        s_w4[t][j4] = w;
    }
    __syncthreads();

    const int d  = tid >> 4;
    const int n4 = tid & 15;

    // stream 32 timesteps; each t is one contiguous 16 KB row (evict-first)
#pragma unroll
    for (int t = 0; t < TC; t++) {
        float  vt = s_v[t][d];
        float4 wt = s_w4[t][n4];
        acc.x += vt * wt.x;
        acc.y += vt * wt.y;
        acc.z += vt * wt.z;
        acc.w += vt * wt.w;
        __stcs(&out[((c * TC + t) * B_DIM + b) * 1024 + tid], acc);
    }
}

// ---------------------------------------------------------------------------
extern "C" void kernel_launch(void* const* d_in, const int* in_sizes, int n_in,
                              void* d_out, int out_size) {
    (void)in_sizes; (void)n_in; (void)out_size;
    const float4* v     = (const float4*)d_in[0];
    const float4* k     = (const float4*)d_in[1];
    const float4* alpha = (const float4*)d_in[2];
    float4* out = (float4*)d_out;

    k_chunk<<<dim3(CH, B_DIM), 512>>>(v, k, alpha);
    k_prep<<<dim3(32, B_DIM), 256>>>();
    k_main<<<dim3(CH, B_DIM), 1024>>>(v, out);
}

// round 17
// speedup vs baseline: 1.4273x; 1.0101x over previous
#include <cuda_runtime.h>
#include <cuda_bf16.h>

// Shapes fixed by problem: T=1024, B=8, D=64, N=64
#define T_DIM 1024
#define B_DIM 8
#define CH    32                   // chunks over T
#define TC    (T_DIM / CH)         // 32 timesteps per chunk
#define EPSV  1e-8f

// Scratch (device globals, allocation-free). float4 types guarantee alignment.
__device__ float  gLogAgg[CH * B_DIM * 64];  // log of per-chunk alpha product
__device__ float4 gWraw4[T_DIM * B_DIM * 16];// k * chunk-local cumprod (2 MB)
__device__ float4 gCraw[CH * B_DIM * 1024];  // unscaled chunk outer sums (4 MB)
__device__ float4 gP[CH * B_DIM * 1024];     // scaled exclusive prefix tiles (4 MB)
__device__ float  gScale[CH * B_DIM * 64];   // decay scale per (chunk, b, n)

__device__ __forceinline__ void pdl_wait() {
    asm volatile("griddepcontrol.wait;" ::: "memory");
}
__device__ __forceinline__ void pdl_launch_dependents() {
    asm volatile("griddepcontrol.launch_dependents;");
}

// ---------------------------------------------------------------------------
// K1: per (c,b): chunk-local multiply-scan -> gWraw4, chunk outer sums -> gCraw,
//     chunk log product -> gLogAgg. 4x4 register tiles, t-split halves.
// grid (CH,B), 512 threads.
// ---------------------------------------------------------------------------
__global__ void __launch_bounds__(512)
k_chunk(const float4* __restrict__ v4,
        const float4* __restrict__ k4,
        const float4* __restrict__ a4) {
    const int c = blockIdx.x, b = blockIdx.y;
    const int tid = threadIdx.x;

    __shared__ float4 s_v4[TC * 16];     // 8 KB  v tile
    __shared__ float4 s_w4[TC * 16];     // 8 KB  alpha -> scan -> w
    __shared__ float  s_tot[8][64];      // 2 KB
    float4* s_tot4 = (float4*)s_tot;

    // one float4 per thread; prefetch k into a register (used after scan)
    float4 kx;
    {
        int t = tid >> 4, j4 = tid & 15;
        int g = ((c * TC + t) * B_DIM + b) * 16 + j4;
        s_v4[tid] = v4[g];
        kx = k4[g];
        float4 a = a4[g];
        a.x = fmaxf(a.x, EPSV); a.y = fmaxf(a.y, EPSV);
        a.z = fmaxf(a.z, EPSV); a.w = fmaxf(a.w, EPSV);
        s_w4[tid] = a;
    }
    __syncthreads();

    // in-place inclusive multiply-scan within 8 groups of 4 t (float4 columns)
    if (tid < 128) {
        int tq = tid >> 4, q = tid & 15;
        float4 r = make_float4(1.f, 1.f, 1.f, 1.f);
#pragma unroll
        for (int i = 0; i < 4; i++) {
            int t = tq * 4 + i;
            float4 x = s_w4[t * 16 + q];
            r.x *= x.x; r.y *= x.y; r.z *= x.z; r.w *= x.w;
            s_w4[t * 16 + q] = r;
        }
        s_tot4[tq * 16 + q] = r;
    }
    __syncthreads();
    if (tid < 64) {                      // exclusive product across 8 groups
        float run = 1.f;
#pragma unroll
        for (int qq = 0; qq < 8; qq++) { float x = s_tot[qq][tid]; s_tot[qq][tid] = run; run *= x; }
        gLogAgg[(c * B_DIM + b) * 64 + tid] = logf(run);
    }
    __syncthreads();

    // finalize on ALL 512 threads: w = k * (localprod * groupprefix)
    {
        int t = tid >> 4, j4 = tid & 15;
        int g = ((c * TC + t) * B_DIM + b) * 16 + j4;
        float4 off = s_tot4[(t >> 2) * 16 + j4];
        float4 w   = s_w4[tid];
        w.x = kx.x * (w.x * off.x);
        w.y = kx.y * (w.y * off.y);
        w.z = kx.z * (w.z * off.z);
        w.w = kx.w * (w.w * off.w);
        s_w4[tid] = w;
        gWraw4[g] = w;
    }
    __syncthreads();

    // outer sums: 4x4 register tiles; halves split t. 16 FMA per 32 B LDS.
    const int half = tid >> 8;           // 0 | 1
    const int idx  = tid & 255;
    const int dq   = idx >> 4;           // 0..15 -> d rows 4dq..4dq+3
    const int nq   = idx & 15;
    float4 a0 = make_float4(0.f,0.f,0.f,0.f), a1 = a0, a2 = a0, a3 = a0;
#pragma unroll
    for (int i = 0; i < 16; i++) {
        int t = half * 16 + i;
        float4 va = s_v4[t * 16 + dq];
        float4 w  = s_w4[t * 16 + nq];
        a0.x += va.x * w.x; a0.y += va.x * w.y; a0.z += va.x * w.z; a0.w += va.x * w.w;
        a1.x += va.y * w.x; a1.y += va.y * w.y; a1.z += va.y * w.z; a1.w += va.y * w.w;
        a2.x += va.z * w.x; a2.y += va.z * w.y; a2.z += va.z * w.z; a2.w += va.z * w.w;
        a3.x += va.w * w.x; a3.y += va.w * w.y; a3.z += va.w * w.z; a3.w += va.w * w.w;
    }
    __syncthreads();                     // v/w tiles now dead; reuse as scratch
    if (half == 1) {
        s_v4[idx * 2 + 0] = a0;  s_v4[idx * 2 + 1] = a1;
        s_w4[idx * 2 + 0] = a2;  s_w4[idx * 2 + 1] = a3;
    }
    __syncthreads();
    if (half == 0) {
        float4 x;
        x = s_v4[idx * 2 + 0]; a0.x += x.x; a0.y += x.y; a0.z += x.z; a0.w += x.w;
        x = s_v4[idx * 2 + 1]; a1.x += x.x; a1.y += x.y; a1.z += x.z; a1.w += x.w;
        x = s_w4[idx * 2 + 0]; a2.x += x.x; a2.y += x.y; a2.z += x.z; a2.w += x.w;
        x = s_w4[idx * 2 + 1]; a3.x += x.x; a3.y += x.y; a3.z += x.z; a3.w += x.w;
        int base = (c * B_DIM + b) * 1024 + nq;
        gCraw[base + (dq * 4 + 0) * 16] = a0;
        gCraw[base + (dq * 4 + 1) * 16] = a1;
        gCraw[base + (dq * 4 + 2) * 16] = a2;
        gCraw[base + (dq * 4 + 3) * 16] = a3;
    }
    pdl_launch_dependents();
}

// ---------------------------------------------------------------------------
// K2: scaled exclusive prefix tiles gP[c] = sum_{cc<c} scale_cc (.) Craw_cc,
//     and (s==0 blocks) persist the scale table to gScale.
// grid (32 slices, B) = 256 blocks, 256 threads. Slice = 32 float4 lanes.
// ---------------------------------------------------------------------------
__global__ void __launch_bounds__(256)
k_prep() {
    const int s = blockIdx.x;            // 0..31: float4-lane slice
    const int b = blockIdx.y;
    const int tid = threadIdx.x;

    __shared__ float  s_sc[CH][64];      // 8 KB scale table
    __shared__ float4 s_c[CH][32];       // 16 KB Craw slice

    pdl_wait();                          // k_chunk data must be visible

    // load Craw slice (coalesced, MLP)
    for (int i = tid; i < CH * 32; i += 256) {
        int cc = i >> 5, l = i & 31;
        s_c[cc][l] = gCraw[(cc * B_DIM + b) * 1024 + s * 32 + l];
    }

    // scale table: coalesced aggregate loads (tid<64 consecutive), reg scan
    if (tid < 64) {
        float a[CH];
#pragma unroll
        for (int cc = 0; cc < CH; cc++)
            a[cc] = __ldg(&gLogAgg[(cc * B_DIM + b) * 64 + tid]);
        float run = 0.f;
#pragma unroll
        for (int cc = 0; cc < CH; cc++) { s_sc[cc][tid] = expf(run); run += a[cc]; }
        float inv = 1.f / (expf(run) + EPSV);
#pragma unroll
        for (int cc = 0; cc < CH; cc++) s_sc[cc][tid] *= inv;
        if (s == 0) {                    // persist for k_main
#pragma unroll
            for (int cc = 0; cc < CH; cc++)
                gScale[(cc * B_DIM + b) * 64 + tid] = s_sc[cc][tid];
        }
    }
    __syncthreads();

    // serial scaled scan down the chunk axis; one float column per thread
    if (tid < 128) {
        const int l = tid >> 2, comp = tid & 3;
        const int n = ((s * 32 + l) & 15) * 4 + comp;    // lane -> n mapping
        float run = 0.f;
#pragma unroll
        for (int cc = 0; cc < CH; cc++) {
            float* p = (float*)&s_c[cc][l] + comp;
            float x = *p;
            *p = run;
            run += s_sc[cc][n] * x;
        }
    }
    __syncthreads();

    // store exclusive prefix slice (coalesced)
    for (int i = tid; i < CH * 32; i += 256) {
        int cc = i >> 5, l = i & 31;
        gP[(cc * B_DIM + b) * 1024 + s * 32 + l] = s_c[cc][l];
    }
    pdl_launch_dependents();
}

// ---------------------------------------------------------------------------
// K3: pure writer. grid (CH,B), 1024 threads. v-load overlaps k_prep via PDL.
// ---------------------------------------------------------------------------
__global__ void __launch_bounds__(1024, 2)
k_main(const float4* __restrict__ v4, float4* __restrict__ out) {
    const int c = blockIdx.x, b = blockIdx.y;
    const int tid = threadIdx.x;

    __shared__ float  s_v[TC][64];       // 8 KB
    __shared__ float4 s_w4[TC][16];      // 8 KB
    __shared__ float  s_scale[64];

    // v tile load is independent of predecessors -> issue before the PDL wait
    if (tid < 512) {
        int t = tid >> 4, j4 = tid & 15;
        ((float4*)s_v)[tid] = v4[((c * TC + t) * B_DIM + b) * 16 + j4];
    }

    pdl_wait();                          // k_prep (and k_chunk) data visible

    if (tid >= 512 && tid < 576) {
        s_scale[tid - 512] = gScale[(c * B_DIM + b) * 64 + (tid - 512)];
    }
    // prefix preload (private, read-once)
    float4 acc = __ldcs(&gP[(c * B_DIM + b) * 1024 + tid]);
    __syncthreads();

    // w load fused with scaling (float4, read-once)
    if (tid < 512) {
        int t = tid >> 4, j4 = tid & 15;
        float4 w  = __ldcs(&gWraw4[((c * TC + t) * B_DIM + b) * 16 + j4]);
        float4 sc = ((float4*)s_scale)[j4];
        w.x *= sc.x; w.y *= sc.y; w.z *= sc.z; w.w *= sc.w;
        s_w4[t][j4] = w;
    }
    __syncthreads();

    const int d  = tid >> 4;
    const int n4 = tid & 15;

    // stream 32 timesteps; each t is one contiguous 16 KB row (evict-first)
#pragma unroll
    for (int t = 0; t < TC; t++) {
        float  vt = s_v[t][d];
        float4 wt = s_w4[t][n4];
        acc.x += vt * wt.x;
        acc.y += vt * wt.y;
        acc.z += vt * wt.z;
        acc.w += vt * wt.w;
        __stcs(&out[((c * TC + t) * B_DIM + b) * 1024 + tid], acc);
    }
}

// ---------------------------------------------------------------------------
extern "C" void kernel_launch(void* const* d_in, const int* in_sizes, int n_in,
                              void* d_out, int out_size) {
    (void)in_sizes; (void)n_in; (void)out_size;
    const float4* v     = (const float4*)d_in[0];
    const float4* k     = (const float4*)d_in[1];
    const float4* alpha = (const float4*)d_in[2];
    float4* out = (float4*)d_out;

    k_chunk<<<dim3(CH, B_DIM), 512>>>(v, k, alpha);

    // PDL launches: secondary may spin up while predecessor drains.
    cudaLaunchAttribute attr[1];
    attr[0].id = cudaLaunchAttributeProgrammaticStreamSerialization;
    attr[0].val.programmaticStreamSerializationAllowed = 1;

    {
        cudaLaunchConfig_t cfg = {};
        cfg.gridDim = dim3(32, B_DIM);
        cfg.blockDim = dim3(256);
        cfg.stream = 0;
        cfg.attrs = attr;
        cfg.numAttrs = 1;
        if (cudaLaunchKernelEx(&cfg, k_prep) != cudaSuccess) {
            (void)cudaGetLastError();            // clear; fall back
            k_prep<<<dim3(32, B_DIM), 256>>>();
        }
    }
    {
        cudaLaunchConfig_t cfg = {};
        cfg.gridDim = dim3(CH, B_DIM);
        cfg.blockDim = dim3(1024);
        cfg.stream = 0;
        cfg.attrs = attr;
        cfg.numAttrs = 1;
        if (cudaLaunchKernelEx(&cfg, k_main, v, out) != cudaSuccess) {
            (void)cudaGetLastError();            // clear; fall back
            k_main<<<dim3(CH, B_DIM), 1024>>>(v, out);
        }
    }
}